// round 9
// baseline (speedup 1.0000x reference)
#include <cuda_runtime.h>
#include <math.h>

// Problem constants
#define NPARTS   2
#define NFULL    24576
#define M        8192
#define SCALE    (1.0f/8192.0f)

// Persistent-kernel config
#define NWORK    148           // resident blocks (1/SM, deadlock-safe on >=148-SM parts)
#define TPB      256
#define NWARP    8

// Tile config: 512 i x 256 j
#define TI       512
#define TJ       256
#define IPT      16            // 16 i-regs/thread -> warp covers 512 i
#define JPW      (TJ/NWARP)    // 32 j per warp
#define NTI      (M/TI)        // 16
#define NTJ      (M/TJ)        // 32
#define T_TILES  (NPARTS*NTI*NTJ)   // 1024

#define INF_BITS 0x7f800000u

// Scratch (allocation-free: __device__ globals, zero-initialized at load)
__device__ float4 g_x[NPARTS][M];              // transformed cad: (x,y,z,|x|^2)
__device__ float4 g_y[NPARTS][M];              // cam: (-2x,-2y,-2z,|y|^2)
__device__ unsigned int g_rowmin[NPARTS][M];   // min_j d2 bits
__device__ unsigned int g_colmin[NPARTS][M];   // min_i d2 bits
__device__ float        g_sums[4];             // row p0, row p1, col p0, col p1
__device__ unsigned int g_ticket;
__device__ unsigned int g_c0, g_c1, g_c2;

// ---------------------------------------------------------------------------
__device__ __forceinline__ void make_T(const float* __restrict__ q4,
                                       const float* __restrict__ t3, float* T) {
    float n = sqrtf(q4[0]*q4[0] + q4[1]*q4[1] + q4[2]*q4[2] + q4[3]*q4[3]);
    float a = q4[0]/n, b = q4[1]/n, c = q4[2]/n, d = q4[3]/n;
    T[0] = 1.f - 2.f*c*c - 2.f*d*d; T[1] = 2.f*b*c - 2.f*a*d;       T[2]  = 2.f*a*c + 2.f*b*d;       T[3]  = t3[0];
    T[4] = 2.f*b*c + 2.f*a*d;       T[5] = 1.f - 2.f*b*b - 2.f*d*d; T[6]  = 2.f*c*d - 2.f*a*b;       T[7]  = t3[1];
    T[8] = 2.f*b*d - 2.f*a*c;       T[9] = 2.f*a*b + 2.f*c*d;       T[10] = 1.f - 2.f*b*b - 2.f*c*c; T[11] = t3[2];
}

// Spin grid-barrier: all NWORK blocks resident by construction.
__device__ __forceinline__ void grid_barrier(unsigned int* c) {
    __threadfence();                 // release: my writes visible before arrive
    __syncthreads();
    if (threadIdx.x == 0) {
        atomicAdd(c, 1u);
        while (*(volatile unsigned int*)c < NWORK) __nanosleep(128);
    }
    __syncthreads();
    __threadfence();                 // acquire
}

// ---------------------------------------------------------------------------
// Kernel 0: reset counters/sums, init min arrays, zero output tail
// ---------------------------------------------------------------------------
__global__ void k_init(float* __restrict__ out, int out_size) {
    int idx = blockIdx.x * blockDim.x + threadIdx.x;   // 64*256 = 16384 threads
    ((unsigned int*)g_rowmin)[idx]          = INF_BITS;
    ((unsigned int*)g_rowmin)[idx + 16384]  = INF_BITS;   // == g_colmin? no:
    // NOTE: rowmin and colmin are distinct arrays; handle each explicitly.
    // (the line above covers rowmin[16384..32767] which is part1 rowmin)
    ((unsigned int*)g_colmin)[idx]          = INF_BITS;
    ((unsigned int*)g_colmin)[idx + 16384 - 16384] = INF_BITS; // idempotent dup
    if (idx == 0) {
        g_ticket = 0u; g_c0 = 0u; g_c1 = 0u; g_c2 = 0u;
        g_sums[0] = g_sums[1] = g_sums[2] = g_sums[3] = 0.f;
    }
    for (int i = 34 + idx; i < out_size; i += 64 * 256) out[i] = 0.0f;
}

// ---------------------------------------------------------------------------
// Kernel 1: persistent fused pipeline
//   Phase A: pack   | barrier | Phase B: ticketed chamfer tiles | barrier |
//   Phase C: reduce + last-block final
// ---------------------------------------------------------------------------
__global__ __launch_bounds__(TPB) void k_main(
        const float* __restrict__ cam, const float* __restrict__ cad,
        const float* __restrict__ w,   const float* __restrict__ quat,
        const float* __restrict__ tra, const float* __restrict__ jaxes,
        float* __restrict__ out) {
    __shared__ float4 ytile[TJ];
    __shared__ unsigned int rowred[TI];
    __shared__ int s_ticket;

    int tid  = threadIdx.x;
    int wix  = tid >> 5;
    int lane = tid & 31;
    int gidx = blockIdx.x * TPB + tid;       // 0..37887

    // ---- Phase A: pack ----
    if (gidx < NPARTS * M) {
        int p = gidx >> 13;
        int m = gidx & (M - 1);
        long off = ((long)p * NFULL + 3L * m) * 3L;
        float T[12];
        make_T(quat + 4*p, tra + 3*p, T);
        const float* cp = cad + off;
        float x = cp[0], y = cp[1], z = cp[2];
        float tx = T[0]*x + T[1]*y + T[2]*z  + T[3];
        float ty = T[4]*x + T[5]*y + T[6]*z  + T[7];
        float tz = T[8]*x + T[9]*y + T[10]*z + T[11];
        g_x[p][m] = make_float4(tx, ty, tz, tx*tx + ty*ty + tz*tz);
        const float* qp = cam + off;
        float cx = qp[0], cy = qp[1], cz = qp[2];
        g_y[p][m] = make_float4(-2.f*cx, -2.f*cy, -2.f*cz, cx*cx + cy*cy + cz*cz);
    }

    grid_barrier(&g_c0);

    // ---- Phase B: ticketed tiles ----
    for (;;) {
        if (tid == 0) s_ticket = (int)atomicAdd(&g_ticket, 1u);
        __syncthreads();                      // also protects ytile/rowred reuse
        int t = s_ticket;
        if (t >= T_TILES) break;
        int jb   = t & (NTJ - 1);
        int ib   = (t >> 5) & (NTI - 1);
        int part = t >> 9;
        const float4* __restrict__ X = g_x[part];
        const float4* __restrict__ Y = g_y[part];
        int ibase = ib * TI, jbase = jb * TJ;

        float xr[IPT], yr[IPT], zr[IPT], sr[IPT], row[IPT];
        #pragma unroll
        for (int k = 0; k < IPT; k++) {
            float4 v = X[ibase + k * 32 + lane];
            xr[k] = v.x; yr[k] = v.y; zr[k] = v.z; sr[k] = v.w;
            row[k] = __int_as_float(INF_BITS);
        }
        ytile[tid] = Y[jbase + tid];
        rowred[tid]       = INF_BITS;
        rowred[tid + 256] = INF_BITS;
        __syncthreads();

        #pragma unroll 2
        for (int mm = 0; mm < JPW; mm++) {
            int jl = wix + NWARP * mm;
            float4 y4 = ytile[jl];            // LDS.128 broadcast
            float col = __int_as_float(INF_BITS);
            #pragma unroll
            for (int k = 0; k < IPT; k++) {
                float s = fmaf(y4.x, xr[k],
                          fmaf(y4.y, yr[k],
                          fmaf(y4.z, zr[k], sr[k])));   // -2x.y + |x|^2
                row[k] = fminf(row[k], s + y4.w);
                col    = fminf(col, s);
            }
            #pragma unroll
            for (int o = 16; o > 0; o >>= 1)
                col = fminf(col, __shfl_xor_sync(0xffffffffu, col, o));
            if (lane == 0) {
                float v = fmaxf(col + y4.w, 0.0f);
                atomicMin(&g_colmin[part][jbase + jl], __float_as_uint(v));
            }
        }

        #pragma unroll
        for (int k = 0; k < IPT; k++) {
            float v = fmaxf(row[k], 0.0f);
            atomicMin(&rowred[k * 32 + lane], __float_as_uint(v));
        }
        __syncthreads();
        atomicMin(&g_rowmin[part][ibase + tid],       rowred[tid]);
        atomicMin(&g_rowmin[part][ibase + tid + 256], rowred[tid + 256]);
    }

    grid_barrier(&g_c1);

    // ---- Phase C: reduce ----
    if (gidx < 2 * NPARTS * M) {
        unsigned int bits = (gidx < NPARTS * M)
            ? ((const unsigned int*)g_rowmin)[gidx]
            : ((const unsigned int*)g_colmin)[gidx - NPARTS * M];
        float s = sqrtf(__uint_as_float(bits));
        #pragma unroll
        for (int o = 16; o > 0; o >>= 1)
            s += __shfl_xor_sync(0xffffffffu, s, o);
        if (lane == 0) atomicAdd(&g_sums[gidx >> 13], s);   // warp-uniform sidx
    }
    __syncthreads();

    if (tid == 0) {
        __threadfence();
        unsigned int r = atomicAdd(&g_c2, 1u);
        if (r == NWORK - 1) {                  // last block: finalize
            __threadfence();
            float T[2][12];
            for (int p = 0; p < 2; p++) {
                make_T(quat + 4*p, tra + 3*p, T[p]);
                for (int rr = 0; rr < 3; rr++)
                    for (int c = 0; c < 4; c++)
                        out[2 + p*16 + rr*4 + c] = T[p][rr*4 + c];
                out[2 + p*16 + 12] = 0.f; out[2 + p*16 + 13] = 0.f;
                out[2 + p*16 + 14] = 0.f; out[2 + p*16 + 15] = 1.f;
            }
            float ss = 0.f;
            for (int c2 = 0; c2 < 2; c2++) {
                for (int rr = 0; rr < 3; rr++) {
                    float v0 = 0.f, v1 = 0.f;
                    for (int k = 0; k < 4; k++) {
                        v0 += T[0][rr*4+k] * jaxes[0*8 + c2*4 + k];
                        v1 += T[1][rr*4+k] * jaxes[1*8 + c2*4 + k];
                    }
                    float dd = v0 - v1;
                    ss += dd * dd;
                }
                float d3 = jaxes[0*8 + c2*4 + 3] - jaxes[1*8 + c2*4 + 3];
                ss += d3 * d3;      // row 3 of the 4x4 transforms
            }
            float ek = 1.f / (1.f + expf(5.f * sqrtf(ss)));
            out[1] = ek;
            volatile float* vs = g_sums;
            float eg = 0.f;
            for (int p = 0; p < 2; p++)
                eg += w[p] * ((vs[p] + vs[2 + p]) * SCALE);
            out[0] = eg + w[NPARTS] * ek;
        }
    }
}

// ---------------------------------------------------------------------------
extern "C" void kernel_launch(void* const* d_in, const int* in_sizes, int n_in,
                              void* d_out, int out_size) {
    const float* cam  = (const float*)d_in[0];
    const float* cad  = (const float*)d_in[1];
    const float* w    = (const float*)d_in[2];
    const float* quat = (const float*)d_in[3];
    const float* tra  = (const float*)d_in[4];
    const float* jax_ = (const float*)d_in[5];
    float* out = (float*)d_out;

    k_init<<<64, 256>>>(out, out_size);
    k_main<<<NWORK, TPB>>>(cam, cad, w, quat, tra, jax_, out);
}

// round 10
// speedup vs baseline: 1.7600x; 1.7600x over previous
#include <cuda_runtime.h>
#include <math.h>

// Problem constants
#define NPARTS   2
#define NFULL    24576
#define M        8192
#define SCALE    (1.0f/8192.0f)

// Chamfer config: 1024-i strips (warp-covered), 128-j tiles, static chunks
#define TPB      256
#define NWARP    8
#define IPT      32            // warp covers 32*32 = 1024 i
#define TI       1024
#define TJ       128
#define JPW      (TJ/NWARP)    // 16 j per warp per tile
#define NTI      (M/TI)        // 8
#define NTJ      (M/TJ)        // 64
#define T_TILES  (NPARTS*NTI*NTJ)   // 1024
#define NBLK     148

#define INF_BITS 0x7f800000u

// Scratch (allocation-free: __device__ globals)
__device__ float4 g_x[NPARTS][M];              // transformed cad: (x,y,z,|x|^2)
__device__ float4 g_y[NPARTS][M];              // cam: (-2x,-2y,-2z,|y|^2)
__device__ unsigned int g_rowmin[NPARTS][M];   // min_j d2 bits
__device__ unsigned int g_colmin[NPARTS][M];   // min_i d2 bits
__device__ float        g_sums[4];             // row p0, row p1, col p0, col p1
__device__ unsigned int g_done;

// ---------------------------------------------------------------------------
__device__ __forceinline__ void make_T(const float* __restrict__ q4,
                                       const float* __restrict__ t3, float* T) {
    float n = sqrtf(q4[0]*q4[0] + q4[1]*q4[1] + q4[2]*q4[2] + q4[3]*q4[3]);
    float a = q4[0]/n, b = q4[1]/n, c = q4[2]/n, d = q4[3]/n;
    T[0] = 1.f - 2.f*c*c - 2.f*d*d; T[1] = 2.f*b*c - 2.f*a*d;       T[2]  = 2.f*a*c + 2.f*b*d;       T[3]  = t3[0];
    T[4] = 2.f*b*c + 2.f*a*d;       T[5] = 1.f - 2.f*b*b - 2.f*d*d; T[6]  = 2.f*c*d - 2.f*a*b;       T[7]  = t3[1];
    T[8] = 2.f*b*d - 2.f*a*c;       T[9] = 2.f*a*b + 2.f*c*d;       T[10] = 1.f - 2.f*b*b - 2.f*c*c; T[11] = t3[2];
}

// ---------------------------------------------------------------------------
// Kernel 1: pack + init mins/sums/counter + zero out tail. 128x256 threads.
// ---------------------------------------------------------------------------
__global__ void k_pack(const float* __restrict__ cam,
                       const float* __restrict__ cad,
                       const float* __restrict__ quat,
                       const float* __restrict__ tra,
                       float* __restrict__ out, int out_size) {
    int idx = blockIdx.x * blockDim.x + threadIdx.x;   // 0..32767
    if (idx < NPARTS * M) ((unsigned int*)g_rowmin)[idx] = INF_BITS;
    else                  ((unsigned int*)g_colmin)[idx - NPARTS*M] = INF_BITS;
    if (idx < 4) g_sums[idx] = 0.0f;
    if (idx == 4) g_done = 0u;
    for (int i = 34 + idx; i < out_size; i += 128 * 256) out[i] = 0.0f;

    if (idx < NPARTS * M) {
        int p = idx >> 13;
        int m = idx & (M - 1);
        long off = ((long)p * NFULL + 3L * m) * 3L;
        float T[12];
        make_T(quat + 4*p, tra + 3*p, T);
        const float* cp = cad + off;
        float x = cp[0], y = cp[1], z = cp[2];
        float tx = T[0]*x + T[1]*y + T[2]*z  + T[3];
        float ty = T[4]*x + T[5]*y + T[6]*z  + T[7];
        float tz = T[8]*x + T[9]*y + T[10]*z + T[11];
        g_x[p][m] = make_float4(tx, ty, tz, tx*tx + ty*ty + tz*tz);
        const float* qp = cam + off;
        float cx = qp[0], cy = qp[1], cz = qp[2];
        g_y[p][m] = make_float4(-2.f*cx, -2.f*cy, -2.f*cz, cx*cx + cy*cy + cz*cz);
    }
}

// ---------------------------------------------------------------------------
// Kernel 2: fused chamfer, 148 blocks, static contiguous tile chunks.
//   tile t: part = t>>9, ib = (t>>6)&7, jb = t&63  (jb-major within segment)
//   Row mins persist in registers across a block's tiles within one
//   (part,ib) segment; flushed on segment change (at most once per block).
// ---------------------------------------------------------------------------
__global__ __launch_bounds__(TPB) void k_chamfer() {
    __shared__ float4 ytile[TJ];
    __shared__ unsigned int rowred[TI];

    int tid  = threadIdx.x;
    int wix  = tid >> 5;
    int lane = tid & 31;
    int b    = blockIdx.x;

    int start = (b * T_TILES) / NBLK;
    int end   = ((b + 1) * T_TILES) / NBLK;

    float xr[IPT], yr[IPT], zr[IPT], sr[IPT], row[IPT];
    int cur_seg = -1;

    // init rowred for first use
    #pragma unroll
    for (int s2 = 0; s2 < TI / TPB; s2++) rowred[tid + s2 * TPB] = INF_BITS;

    for (int t = start; t < end; t++) {
        int part = t >> 9;
        int ib   = (t >> 6) & (NTI - 1);
        int jb   = t & (NTJ - 1);
        int seg  = t >> 6;

        if (seg != cur_seg) {
            if (cur_seg >= 0) {
                // flush rows of previous segment
                int pprev = cur_seg >> 3;
                int ibprev = cur_seg & (NTI - 1);
                #pragma unroll
                for (int k = 0; k < IPT; k++) {
                    float v = fmaxf(row[k], 0.0f);
                    atomicMin(&rowred[k * 32 + lane], __float_as_uint(v));
                }
                __syncthreads();
                #pragma unroll
                for (int s2 = 0; s2 < TI / TPB; s2++) {
                    int il = tid + s2 * TPB;
                    atomicMin(&g_rowmin[pprev][ibprev * TI + il], rowred[il]);
                    rowred[il] = INF_BITS;
                }
            }
            cur_seg = seg;
            int ibase = ib * TI;
            #pragma unroll
            for (int k = 0; k < IPT; k++) {
                float4 v = g_x[part][ibase + k * 32 + lane];
                xr[k] = v.x; yr[k] = v.y; zr[k] = v.z; sr[k] = v.w;
                row[k] = __int_as_float(INF_BITS);
            }
        }

        // stage j tile (sync guards previous readers AND rowred re-init)
        __syncthreads();
        if (tid < TJ) ytile[tid] = g_y[part][jb * TJ + tid];
        __syncthreads();

        #pragma unroll 2
        for (int mm = 0; mm < JPW; mm++) {
            int jl = wix + NWARP * mm;
            float4 y4 = ytile[jl];            // LDS.128 broadcast, conflict-free
            float col = __int_as_float(INF_BITS);
            #pragma unroll
            for (int k = 0; k < IPT; k++) {
                float s = fmaf(y4.x, xr[k],
                          fmaf(y4.y, yr[k],
                          fmaf(y4.z, zr[k], sr[k])));   // -2x.y + |x|^2
                row[k] = fminf(row[k], s + y4.w);        // full d2
                col    = fminf(col, s);
            }
            #pragma unroll
            for (int o = 16; o > 0; o >>= 1)
                col = fminf(col, __shfl_xor_sync(0xffffffffu, col, o));
            if (lane == 0) {
                float v = fmaxf(col + y4.w, 0.0f);
                atomicMin(&g_colmin[part][jb * TJ + jl], __float_as_uint(v));
            }
        }
    }

    // final flush
    if (cur_seg >= 0) {
        int pprev = cur_seg >> 3;
        int ibprev = cur_seg & (NTI - 1);
        #pragma unroll
        for (int k = 0; k < IPT; k++) {
            float v = fmaxf(row[k], 0.0f);
            atomicMin(&rowred[k * 32 + lane], __float_as_uint(v));
        }
        __syncthreads();
        #pragma unroll
        for (int s2 = 0; s2 < TI / TPB; s2++) {
            int il = tid + s2 * TPB;
            atomicMin(&g_rowmin[pprev][ibprev * TI + il], rowred[il]);
        }
    }
}

// ---------------------------------------------------------------------------
// Kernel 3: reduce sums + last-block finalize (transforms/e_kin/objective)
// ---------------------------------------------------------------------------
__global__ void k_reduce_final(const float* __restrict__ w,
                               const float* __restrict__ quat,
                               const float* __restrict__ tra,
                               const float* __restrict__ jaxes,
                               float* __restrict__ out) {
    int bi    = blockIdx.x;               // 0..31
    int sidx  = bi >> 3;                  // 0..3
    int p     = sidx & 1;
    int chunk = bi & 7;
    const unsigned int* __restrict__ mv =
        ((bi < 16) ? g_rowmin[p] : g_colmin[p]) + chunk * 1024;
    float s = 0.f;
    #pragma unroll
    for (int r = 0; r < 4; r++)
        s += sqrtf(__uint_as_float(mv[threadIdx.x + r * 256]));
    #pragma unroll
    for (int o = 16; o > 0; o >>= 1)
        s += __shfl_xor_sync(0xffffffffu, s, o);
    __shared__ float sh[8];
    if ((threadIdx.x & 31) == 0) sh[threadIdx.x >> 5] = s;
    __syncthreads();
    if (threadIdx.x < 8) {
        float v = sh[threadIdx.x];
        #pragma unroll
        for (int o = 4; o > 0; o >>= 1)
            v += __shfl_xor_sync(0xffu, v, o);
        if (threadIdx.x == 0) atomicAdd(&g_sums[sidx], v);
    }

    if (threadIdx.x == 0) {
        __threadfence();
        unsigned int r = atomicAdd(&g_done, 1u);
        if (r == 31u) {                    // last block out: finalize
            __threadfence();
            float T[2][12];
            for (int pp = 0; pp < 2; pp++) {
                make_T(quat + 4*pp, tra + 3*pp, T[pp]);
                for (int rr = 0; rr < 3; rr++)
                    for (int c = 0; c < 4; c++)
                        out[2 + pp*16 + rr*4 + c] = T[pp][rr*4 + c];
                out[2 + pp*16 + 12] = 0.f; out[2 + pp*16 + 13] = 0.f;
                out[2 + pp*16 + 14] = 0.f; out[2 + pp*16 + 15] = 1.f;
            }
            float ss = 0.f;
            for (int c2 = 0; c2 < 2; c2++) {
                for (int rr = 0; rr < 3; rr++) {
                    float v0 = 0.f, v1 = 0.f;
                    for (int k = 0; k < 4; k++) {
                        v0 += T[0][rr*4+k] * jaxes[0*8 + c2*4 + k];
                        v1 += T[1][rr*4+k] * jaxes[1*8 + c2*4 + k];
                    }
                    float dd = v0 - v1;
                    ss += dd * dd;
                }
                float d3 = jaxes[0*8 + c2*4 + 3] - jaxes[1*8 + c2*4 + 3];
                ss += d3 * d3;            // row 3 of the 4x4 transforms
            }
            float ek = 1.f / (1.f + expf(5.f * sqrtf(ss)));
            out[1] = ek;
            volatile float* vs = g_sums;
            float eg = 0.f;
            for (int pp = 0; pp < 2; pp++)
                eg += w[pp] * ((vs[pp] + vs[2 + pp]) * SCALE);
            out[0] = eg + w[NPARTS] * ek;
        }
    }
}

// ---------------------------------------------------------------------------
extern "C" void kernel_launch(void* const* d_in, const int* in_sizes, int n_in,
                              void* d_out, int out_size) {
    const float* cam  = (const float*)d_in[0];
    const float* cad  = (const float*)d_in[1];
    const float* w    = (const float*)d_in[2];
    const float* quat = (const float*)d_in[3];
    const float* tra  = (const float*)d_in[4];
    const float* jax_ = (const float*)d_in[5];
    float* out = (float*)d_out;

    k_pack<<<128, 256>>>(cam, cad, quat, tra, out, out_size);
    k_chamfer<<<NBLK, TPB>>>();
    k_reduce_final<<<32, 256>>>(w, quat, tra, jax_, out);
}

// round 11
// speedup vs baseline: 2.1803x; 1.2388x over previous
#include <cuda_runtime.h>
#include <math.h>

// Problem constants
#define NPARTS   2
#define NFULL    24576
#define M        8192
#define SCALE    (1.0f/8192.0f)

// Single persistent kernel: 144 blocks = 2 parts x 8 i-strips x 9 j-ranges
#define NBLK     144
#define TPB      256
#define NWARP    8
#define IPT      32            // warp covers 32*32 = 1024 i
#define TI       1024
#define SLABJ    9             // j-ranges per slab
#define JMAX     928           // ranges: 8 x 928 + 1 x 768 = 8192

#define INF_BITS 0x7f800000u

// Scratch (__device__ globals; no per-run init needed — all slots overwritten
// or handled via monotonic counters)
__device__ unsigned int g_rowpart[NPARTS][SLABJ][M]; // per-j-range row-min slices
__device__ unsigned int g_colpart[NPARTS][8][M];     // per-i-strip col-min slices
__device__ float        g_sums[4];                   // row p0,p1, col p0,p1
__device__ unsigned int g_bar;    // monotonic grid barrier counter
__device__ unsigned int g_done;   // monotonic completion counter

// ---------------------------------------------------------------------------
__device__ __forceinline__ void make_T(const float* __restrict__ q4,
                                       const float* __restrict__ t3, float* T) {
    float n = sqrtf(q4[0]*q4[0] + q4[1]*q4[1] + q4[2]*q4[2] + q4[3]*q4[3]);
    float a = q4[0]/n, b = q4[1]/n, c = q4[2]/n, d = q4[3]/n;
    T[0] = 1.f - 2.f*c*c - 2.f*d*d; T[1] = 2.f*b*c - 2.f*a*d;       T[2]  = 2.f*a*c + 2.f*b*d;       T[3]  = t3[0];
    T[4] = 2.f*b*c + 2.f*a*d;       T[5] = 1.f - 2.f*b*b - 2.f*d*d; T[6]  = 2.f*c*d - 2.f*a*b;       T[7]  = t3[1];
    T[8] = 2.f*b*d - 2.f*a*c;       T[9] = 2.f*a*b + 2.f*c*d;       T[10] = 1.f - 2.f*b*b - 2.f*c*c; T[11] = t3[2];
}

// ---------------------------------------------------------------------------
__global__ __launch_bounds__(TPB, 1) void k_all(
        const float* __restrict__ cam, const float* __restrict__ cad,
        const float* __restrict__ w,   const float* __restrict__ quat,
        const float* __restrict__ tra, const float* __restrict__ jaxes,
        float* __restrict__ out, int out_size) {
    __shared__ float4 ytile[JMAX];          // 14848 B
    __shared__ unsigned int rowred[TI];     //  4096 B
    __shared__ float sh[NWARP];

    int tid  = threadIdx.x;
    int wix  = tid >> 5;
    int lane = tid & 31;
    int b    = blockIdx.x;
    int part = b / 72;
    int r    = b % 72;
    int ib   = r / SLABJ;
    int jr   = r % SLABJ;
    int j0   = jr * JMAX;
    int jlen = (jr == SLABJ - 1) ? (M - (SLABJ - 1) * JMAX) : JMAX;  // 768 or 928

    // block 0: zero sums + out tail (ordered before phase C by the barrier)
    if (b == 0) {
        if (tid < 4) g_sums[tid] = 0.0f;
        for (int i = 34 + tid; i < out_size; i += TPB) out[i] = 0.0f;
    }

    // ---- Phase A: self-pack ----
    float T[12];
    make_T(quat + 4 * part, tra + 3 * part, T);

    // X strip (transformed cad) into registers: i = ib*1024 + k*32 + lane
    float xr[IPT], yr[IPT], zr[IPT], sr[IPT], row[IPT];
    {
        const float* cbase = cad + (long)part * (NFULL * 3) + (long)(ib * TI + lane) * 9;
        #pragma unroll
        for (int k = 0; k < IPT; k++) {
            const float* cp = cbase + k * (32 * 9);
            float x = cp[0], y = cp[1], z = cp[2];
            float tx = T[0]*x + T[1]*y + T[2]*z  + T[3];
            float ty = T[4]*x + T[5]*y + T[6]*z  + T[7];
            float tz = T[8]*x + T[9]*y + T[10]*z + T[11];
            xr[k] = tx; yr[k] = ty; zr[k] = tz;
            sr[k] = tx*tx + ty*ty + tz*tz;
            row[k] = __int_as_float(INF_BITS);
        }
    }

    // Y range (cam, transform-free) into smem, prescaled by -2
    {
        const float* qbase = cam + (long)part * (NFULL * 3) + (long)j0 * 9;
        for (int t = tid; t < jlen; t += TPB) {
            const float* qp = qbase + t * 9;
            float cx = qp[0], cy = qp[1], cz = qp[2];
            ytile[t] = make_float4(-2.f*cx, -2.f*cy, -2.f*cz, cx*cx + cy*cy + cz*cz);
        }
    }
    #pragma unroll
    for (int s2 = 0; s2 < TI / TPB; s2++) rowred[tid + s2 * TPB] = INF_BITS;
    __syncthreads();     // the ONE sync before the hot loop (R4 shape)

    // ---- Phase B: chamfer sweep (per warp: j = wix, wix+8, ...) ----
    int nj = jlen >> 3;                   // 116 or 96 per warp
    #pragma unroll 2
    for (int mm = 0; mm < nj; mm++) {
        int jl = wix + NWARP * mm;
        float4 y4 = ytile[jl];            // LDS.128 broadcast, conflict-free
        float col = __int_as_float(INF_BITS);
        #pragma unroll
        for (int k = 0; k < IPT; k++) {
            float s = fmaf(y4.x, xr[k],
                      fmaf(y4.y, yr[k],
                      fmaf(y4.z, zr[k], sr[k])));   // -2 x.y + |x|^2
            row[k] = fminf(row[k], s + y4.w);        // full d2
            col    = fminf(col, s);
        }
        #pragma unroll
        for (int o = 16; o > 0; o >>= 1)
            col = fminf(col, __shfl_xor_sync(0xffffffffu, col, o));
        if (lane == 0) {
            float v = fmaxf(col + y4.w, 0.0f);
            g_colpart[part][ib][j0 + jl] = __float_as_uint(v);   // plain STG
        }
    }

    // merge row partials across warps, store slice (plain STG, full coverage)
    #pragma unroll
    for (int k = 0; k < IPT; k++) {
        float v = fmaxf(row[k], 0.0f);
        atomicMin(&rowred[k * 32 + lane], __float_as_uint(v));
    }
    __syncthreads();
    #pragma unroll
    for (int s2 = 0; s2 < TI / TPB; s2++) {
        int il = tid + s2 * TPB;
        g_rowpart[part][jr][ib * TI + il] = rowred[il];
    }

    // ---- grid barrier (monotonic: replay-safe, no reset kernel) ----
    __threadfence();
    __syncthreads();
    if (tid == 0) {
        unsigned int old = atomicAdd(&g_bar, 1u);
        unsigned int target = (old / NBLK + 1u) * NBLK;
        while (*(volatile unsigned int*)&g_bar < target) __nanosleep(64);
    }
    __syncthreads();
    __threadfence();

    // ---- Phase C: reduce mins -> sums ----
    int gidx = b * TPB + tid;       // blocks 0..127 participate (32768 entries)
    float val = 0.0f;
    if (gidx < 2 * NPARTS * M) {
        unsigned int mb = INF_BITS;
        if (gidx < NPARTS * M) {
            int p = gidx >> 13, i = gidx & (M - 1);
            #pragma unroll
            for (int s = 0; s < SLABJ; s++)
                mb = min(mb, __ldcg(&g_rowpart[p][s][i]));
        } else {
            int g2 = gidx - NPARTS * M;
            int p = g2 >> 13, j = g2 & (M - 1);
            #pragma unroll
            for (int s = 0; s < 8; s++)
                mb = min(mb, __ldcg(&g_colpart[p][s][j]));
        }
        val = sqrtf(__uint_as_float(mb));
    }
    if (gidx < 2 * NPARTS * M) {
        #pragma unroll
        for (int o = 16; o > 0; o >>= 1)
            val += __shfl_xor_sync(0xffffffffu, val, o);
        if (lane == 0) sh[wix] = val;
    }
    __syncthreads();
    if (tid == 0) {
        if (gidx < 2 * NPARTS * M) {      // sidx uniform per block
            float s = 0.f;
            #pragma unroll
            for (int k2 = 0; k2 < NWARP; k2++) s += sh[k2];
            atomicAdd(&g_sums[gidx >> 13], s);
        }
        __threadfence();
        unsigned int old = atomicAdd(&g_done, 1u);
        if (old % NBLK == NBLK - 1) {     // last block out: finalize
            __threadfence();
            float TT[2][12];
            for (int pp = 0; pp < 2; pp++) {
                make_T(quat + 4*pp, tra + 3*pp, TT[pp]);
                for (int rr = 0; rr < 3; rr++)
                    for (int c = 0; c < 4; c++)
                        out[2 + pp*16 + rr*4 + c] = TT[pp][rr*4 + c];
                out[2 + pp*16 + 12] = 0.f; out[2 + pp*16 + 13] = 0.f;
                out[2 + pp*16 + 14] = 0.f; out[2 + pp*16 + 15] = 1.f;
            }
            float ss = 0.f;
            for (int c2 = 0; c2 < 2; c2++) {
                for (int rr = 0; rr < 3; rr++) {
                    float v0 = 0.f, v1 = 0.f;
                    for (int k2 = 0; k2 < 4; k2++) {
                        v0 += TT[0][rr*4+k2] * jaxes[0*8 + c2*4 + k2];
                        v1 += TT[1][rr*4+k2] * jaxes[1*8 + c2*4 + k2];
                    }
                    float dd = v0 - v1;
                    ss += dd * dd;
                }
                float d3 = jaxes[0*8 + c2*4 + 3] - jaxes[1*8 + c2*4 + 3];
                ss += d3 * d3;            // row 3 of the 4x4 transforms
            }
            float ek = 1.f / (1.f + expf(5.f * sqrtf(ss)));
            out[1] = ek;
            volatile float* vs = g_sums;
            float eg = 0.f;
            for (int pp = 0; pp < 2; pp++)
                eg += w[pp] * ((vs[pp] + vs[2 + pp]) * SCALE);
            out[0] = eg + w[NPARTS] * ek;
        }
    }
}

// ---------------------------------------------------------------------------
extern "C" void kernel_launch(void* const* d_in, const int* in_sizes, int n_in,
                              void* d_out, int out_size) {
    const float* cam  = (const float*)d_in[0];
    const float* cad  = (const float*)d_in[1];
    const float* w    = (const float*)d_in[2];
    const float* quat = (const float*)d_in[3];
    const float* tra  = (const float*)d_in[4];
    const float* jax_ = (const float*)d_in[5];
    float* out = (float*)d_out;

    k_all<<<NBLK, TPB>>>(cam, cad, w, quat, tra, jax_, out, out_size);
}